// round 14
// baseline (speedup 1.0000x reference)
#include <cuda_runtime.h>
#include <cuda_bf16.h>
#include <cuda_fp16.h>
#include <math.h>

#define BDIM  2
#define TSEQ  2048
#define CDIM  2048
#define NHEAD 16
#define HD    128

// ---------------- device-global scratch (no runtime allocation) ----------------
__device__ unsigned g_xh [(size_t)BDIM * TSEQ * CDIM / 2];      // x fp16 pairs
__device__ unsigned g_wah[(size_t)CDIM * 3 * CDIM / 2];         // w_attn fp16 pairs
__device__ unsigned g_wph[(size_t)CDIM * CDIM / 2];             // w_proj fp16 pairs
__device__ float    g_qkv[(size_t)BDIM * TSEQ * 3 * CDIM];      // qkv fp32
__device__ unsigned g_att[(size_t)BDIM * TSEQ * CDIM / 2];      // att fp16 pairs

// ---------------- helpers ----------------
__device__ __forceinline__ unsigned smem_u32(const void* p) {
    unsigned a;
    asm("{ .reg .u64 t; cvta.to.shared.u64 t, %1; cvt.u32.u64 %0, t; }"
        : "=r"(a) : "l"(p));
    return a;
}

__device__ __forceinline__ unsigned pack2h(float x, float y) {
    unsigned r;
    asm("cvt.rn.f16x2.f32 %0, %1, %2;" : "=r"(r) : "f"(y), "f"(x));
    return r;
}

__device__ __forceinline__ void split2(float x, float y, unsigned& hi, unsigned& lo) {
    unsigned h;
    asm("cvt.rn.bf16x2.f32 %0, %1, %2;" : "=r"(h) : "f"(y), "f"(x));
    float hx = __uint_as_float(h << 16);
    float hy = __uint_as_float(h & 0xffff0000u);
    float rx = x - hx;
    float ry = y - hy;
    unsigned l;
    asm("cvt.rn.bf16x2.f32 %0, %1, %2;" : "=r"(l) : "f"(ry), "f"(rx));
    hi = h; lo = l;
}

// bf16 mma (flash QK)
__device__ __forceinline__ void mma16816(float* d, const unsigned* a, const unsigned* b) {
    asm("mma.sync.aligned.m16n8k16.row.col.f32.bf16.bf16.f32 "
        "{%0,%1,%2,%3}, {%4,%5,%6,%7}, {%8,%9}, {%0,%1,%2,%3};"
        : "+f"(d[0]), "+f"(d[1]), "+f"(d[2]), "+f"(d[3])
        : "r"(a[0]), "r"(a[1]), "r"(a[2]), "r"(a[3]), "r"(b[0]), "r"(b[1]));
}
// fp16 mma (GEMMs + flash PV)
__device__ __forceinline__ void mma16816h(float* d, const unsigned* a, const unsigned* b) {
    asm("mma.sync.aligned.m16n8k16.row.col.f32.f16.f16.f32 "
        "{%0,%1,%2,%3}, {%4,%5,%6,%7}, {%8,%9}, {%0,%1,%2,%3};"
        : "+f"(d[0]), "+f"(d[1]), "+f"(d[2]), "+f"(d[3])
        : "r"(a[0]), "r"(a[1]), "r"(a[2]), "r"(a[3]), "r"(b[0]), "r"(b[1]));
}

__device__ __forceinline__ void ldsm_x4(unsigned* r, unsigned addr) {
    asm volatile("ldmatrix.sync.aligned.m8n8.x4.shared.b16 {%0,%1,%2,%3}, [%4];"
                 : "=r"(r[0]), "=r"(r[1]), "=r"(r[2]), "=r"(r[3]) : "r"(addr));
}
__device__ __forceinline__ void ldsm_x4t(unsigned* r, unsigned addr) {
    asm volatile("ldmatrix.sync.aligned.m8n8.x4.trans.shared.b16 {%0,%1,%2,%3}, [%4];"
                 : "=r"(r[0]), "=r"(r[1]), "=r"(r[2]), "=r"(r[3]) : "r"(addr));
}

__device__ __forceinline__ void cp16(unsigned dst, const void* src) {
    asm volatile("cp.async.cg.shared.global [%0], [%1], 16;" :: "r"(dst), "l"(src) : "memory");
}
__device__ __forceinline__ void cp_commit() {
    asm volatile("cp.async.commit_group;" ::: "memory");
}
template<int N> __device__ __forceinline__ void cp_wait() {
    asm volatile("cp.async.wait_group %0;" :: "n"(N) : "memory");
}

// ---------------------------------------------------------------------------
// fp32 -> fp16 pair conversion (one-time preprocessing)
// ---------------------------------------------------------------------------
__global__ void f2h_kernel(const float2* __restrict__ in, unsigned* __restrict__ out, int n2)
{
    int i = blockIdx.x * blockDim.x + threadIdx.x;
    if (i < n2) {
        float2 v = in[i];
        out[i] = pack2h(v.x, v.y);
    }
}

// ---------------------------------------------------------------------------
// fp16-in GEMM + bias (fp32 accumulate, fp32 out). cp.async 2-stage pipeline.
// Block 128(M) x 256(N), BK=32, 256 threads (8 warps, warp tile 64x64).
// smem/HMMA ratio 172B (vs 256B at 128x128) — breaks the smem co-limit.
// ---------------------------------------------------------------------------
#define GBM 128
#define GBN 256
#define GBK 32
#define ASTRIDE 40      // f16 units per A row (80 B)
#define BSTRIDE 264     // f16 units per B row (528 B; 528 mod 128 = 16, conflict-free)
#define ABYTES (GBM * ASTRIDE * 2)     // 10240
#define BBYTES (GBK * BSTRIDE * 2)     // 16896
#define STAGEB (ABYTES + BBYTES)       // 27136
#define GSMEM  (2 * STAGEB)            // 54272

__global__ void __launch_bounds__(256, 1) gemm_f16cp_kernel(
    const __half* __restrict__ A, const __half* __restrict__ B,
    const float* __restrict__ bias, float* __restrict__ C,
    int M, int N, int K)
{
    extern __shared__ char gsm[];
    const unsigned base = smem_u32(gsm);

    const int tid  = threadIdx.x;
    const int lane = tid & 31;
    const int warp = tid >> 5;
    const int wm   = warp >> 2;      // 0..1  (64 rows each)
    const int wn   = warp & 3;       // 0..3  (64 cols each)
    const int m0   = blockIdx.y * GBM;
    const int n0   = blockIdx.x * GBN;

    float d[4][8][4];
    #pragma unroll
    for (int i = 0; i < 4; i++)
        #pragma unroll
        for (int j = 0; j < 8; j++)
            #pragma unroll
            for (int c = 0; c < 4; c++) d[i][j][c] = 0.f;

    const unsigned aOff = (unsigned)(((wm * 64 + (lane & 15)) * ASTRIDE + (lane >> 4) * 8) * 2);
    const unsigned bOff = (unsigned)(((lane & 15) * BSTRIDE + wn * 64 + ((lane >> 4) & 1) * 8) * 2);

    auto issue = [&](int it, int s) {
        int k0 = it * GBK;
        unsigned st = base + s * STAGEB;
        // A: 512 chunks of 16B (128 rows x 4)
        {   int r = tid >> 2, c = tid & 3;
            cp16(st + r * 80 + c * 16, A + (size_t)(m0 + r) * K + k0 + c * 8); }
        {   int ch = tid + 256; int r = ch >> 2, c = ch & 3;
            cp16(st + r * 80 + c * 16, A + (size_t)(m0 + r) * K + k0 + c * 8); }
        // B: 1024 chunks of 16B (32 rows x 32)
        #pragma unroll
        for (int l = 0; l < 4; l++) {
            int ch = tid + l * 256;
            int r = ch >> 5, c = ch & 31;
            cp16(st + ABYTES + r * 528 + c * 16, B + (size_t)(k0 + r) * N + n0 + c * 8);
        }
        cp_commit();
    };

    const int iters = K / GBK;
    issue(0, 0);

    for (int it = 0; it < iters; it++) {
        const int s = it & 1;
        if (it + 1 < iters) {
            issue(it + 1, s ^ 1);
            cp_wait<1>();
        } else {
            cp_wait<0>();
        }
        __syncthreads();

        const unsigned aB = base + s * STAGEB + aOff;
        const unsigned bB = base + s * STAGEB + ABYTES + bOff;

        #pragma unroll
        for (int kc = 0; kc < GBK; kc += 16) {
            unsigned ah[4][4], bh[4][4];
            #pragma unroll
            for (int tm = 0; tm < 4; tm++)
                ldsm_x4(ah[tm], aB + tm * (16 * ASTRIDE * 2) + kc * 2);
            #pragma unroll
            for (int t2 = 0; t2 < 4; t2++)
                ldsm_x4t(bh[t2], bB + kc * (BSTRIDE * 2) + t2 * 32);
            #pragma unroll
            for (int tm = 0; tm < 4; tm++)
                #pragma unroll
                for (int tn = 0; tn < 8; tn++)
                    mma16816h(d[tm][tn], ah[tm], bh[tn >> 1] + (tn & 1) * 2);
        }
        __syncthreads();
    }

    // epilogue: bias + fp32 store
    const int g = lane >> 2, t4 = lane & 3;
    #pragma unroll
    for (int tn = 0; tn < 8; tn++) {
        int col = n0 + wn * 64 + tn * 8 + t4 * 2;
        float bx = bias[col], by = bias[col + 1];
        #pragma unroll
        for (int tm = 0; tm < 4; tm++) {
            int row0 = m0 + wm * 64 + tm * 16 + g;
            *(float2*)(C + (size_t)row0 * N + col) =
                make_float2(d[tm][tn][0] + bx, d[tm][tn][1] + by);
            *(float2*)(C + (size_t)(row0 + 8) * N + col) =
                make_float2(d[tm][tn][2] + bx, d[tm][tn][3] + by);
        }
    }
}

// ---------------------------------------------------------------------------
// Flash attention (causal): QK = 3-term bf16, PV = 1-term fp16.
// (R12 version, known good: 128 queries x 64-key tiles, 8 warps)
// ---------------------------------------------------------------------------
#define FQ 128
#define FK 64
#define QSTR 136          // 16-bit units per row
#define QSTRU 68          // uint units per row

#define OFF_QH 0
#define OFF_QL (128 * QSTRU)
#define OFF_KH (OFF_QL + 128 * QSTRU)
#define OFF_KL (OFF_KH + 64 * QSTRU)
#define OFF_VH (OFF_KL + 64 * QSTRU)
#define FLASH_SMEM ((OFF_VH + 64 * QSTRU) * 4)   // 121856 bytes

__global__ void __launch_bounds__(256, 1) flash_mma_kernel(
    const float* __restrict__ qkv, unsigned* __restrict__ att)
{
    extern __shared__ unsigned fsm[];
    const unsigned base = smem_u32(fsm);

    const int tid  = threadIdx.x;
    const int lane = tid & 31;
    const int wm   = tid >> 5;          // 0..7 : 16 query rows each
    const int g    = lane >> 2;
    const int t4   = lane & 3;

    const int qi = (int)gridDim.x - 1 - (int)blockIdx.x;   // heavy blocks first
    const int h  = blockIdx.y;
    const int b  = blockIdx.z;
    const int q0 = qi * FQ;
    const float scale_q = 0.08838834764831844f;  // 1/sqrt(128)

    const float* qb = qkv + (size_t)b * TSEQ * 3 * CDIM + h * HD;
    const float* kb = qb + CDIM;
    const float* vb = qb + 2 * CDIM;

    // ---- load + split Q tile (128 x 128), pre-scaled ----
    #pragma unroll
    for (int l = 0; l < 16; l++) {
        int lin = tid + l * 256;
        int r   = lin >> 5;
        int c   = lin & 31;
        float4 v = *(const float4*)(qb + (size_t)(q0 + r) * 3 * CDIM + c * 4);
        unsigned h0, l0, h1, l1;
        split2(v.x * scale_q, v.y * scale_q, h0, l0);
        split2(v.z * scale_q, v.w * scale_q, h1, l1);
        int ui = r * QSTRU + c * 2;
        fsm[OFF_QH + ui] = h0; fsm[OFF_QH + ui + 1] = h1;
        fsm[OFF_QL + ui] = l0; fsm[OFF_QL + ui + 1] = l1;
    }
    __syncthreads();

    unsigned qh[8][4];
    const unsigned aoff = (unsigned)(((wm * 16 + (lane & 15)) * QSTR + (lane >> 4) * 8) * 2);
    #pragma unroll
    for (int ks = 0; ks < 8; ks++)
        ldsm_x4(qh[ks], base + OFF_QH * 4 + aoff + ks * 32);

    float m0r = -INFINITY, m1r = -INFINITY, l0r = 0.f, l1r = 0.f;
    float O[16][4];
    #pragma unroll
    for (int dt = 0; dt < 16; dt++)
        #pragma unroll
        for (int c = 0; c < 4; c++) O[dt][c] = 0.f;

    const unsigned k4Off = (unsigned)(
        (((lane & 7) + ((lane >> 4) & 1) * 8) * QSTR + ((lane >> 3) & 1) * 8) * 2);
    const unsigned v4Off = (unsigned)(
        ((lane & 15) * QSTR + ((lane >> 4) & 1) * 8) * 2);

    const int jmax = 2 * qi + 2;
    for (int j = 0; j < jmax; j++) {
        __syncthreads();
        #pragma unroll
        for (int l = 0; l < 8; l++) {
            int lin = tid + l * 256;
            int r   = lin >> 5;
            int c   = lin & 31;
            size_t goff = (size_t)(j * FK + r) * 3 * CDIM + c * 4;
            int ui = r * QSTRU + c * 2;
            float4 kv = *(const float4*)(kb + goff);
            unsigned h0, lo0, h1, lo1;
            split2(kv.x, kv.y, h0, lo0);
            split2(kv.z, kv.w, h1, lo1);
            fsm[OFF_KH + ui] = h0; fsm[OFF_KH + ui + 1] = h1;
            fsm[OFF_KL + ui] = lo0; fsm[OFF_KL + ui + 1] = lo1;
            float4 vv = *(const float4*)(vb + goff);
            fsm[OFF_VH + ui]     = pack2h(vv.x, vv.y);
            fsm[OFF_VH + ui + 1] = pack2h(vv.z, vv.w);
        }
        __syncthreads();

        // ---- S = Q K^T (3-term bf16) ----
        float S[8][4];
        #pragma unroll
        for (int nt = 0; nt < 8; nt++)
            #pragma unroll
            for (int c = 0; c < 4; c++) S[nt][c] = 0.f;

        #pragma unroll
        for (int ks = 0; ks < 8; ks++) {
            unsigned ql_[4];
            ldsm_x4(ql_, base + OFF_QL * 4 + aoff + ks * 32);
            #pragma unroll
            for (int nt = 0; nt < 8; nt += 2) {
                unsigned koff = k4Off + (unsigned)((nt * 8 * QSTR + ks * 16) * 2);
                unsigned kh4[4], kl4[4];
                ldsm_x4(kh4, base + OFF_KH * 4 + koff);
                ldsm_x4(kl4, base + OFF_KL * 4 + koff);
                mma16816(S[nt],     qh[ks], kh4);
                mma16816(S[nt],     qh[ks], kl4);
                mma16816(S[nt],     ql_,    kh4);
                mma16816(S[nt + 1], qh[ks], kh4 + 2);
                mma16816(S[nt + 1], qh[ks], kl4 + 2);
                mma16816(S[nt + 1], ql_,    kh4 + 2);
            }
        }

        // ---- causal mask ----
        const int rg0 = q0 + wm * 16 + g;
        const int rg1 = rg0 + 8;
        if (j * FK + FK - 1 > q0 + wm * 16) {
            #pragma unroll
            for (int nt = 0; nt < 8; nt++) {
                int kg = j * FK + nt * 8 + 2 * t4;
                if (kg     > rg0) S[nt][0] = -INFINITY;
                if (kg + 1 > rg0) S[nt][1] = -INFINITY;
                if (kg     > rg1) S[nt][2] = -INFINITY;
                if (kg + 1 > rg1) S[nt][3] = -INFINITY;
            }
        }

        // ---- online softmax ----
        float mx0 = -INFINITY, mx1 = -INFINITY;
        #pragma unroll
        for (int nt = 0; nt < 8; nt++) {
            mx0 = fmaxf(mx0, fmaxf(S[nt][0], S[nt][1]));
            mx1 = fmaxf(mx1, fmaxf(S[nt][2], S[nt][3]));
        }
        mx0 = fmaxf(mx0, __shfl_xor_sync(0xffffffffu, mx0, 1));
        mx0 = fmaxf(mx0, __shfl_xor_sync(0xffffffffu, mx0, 2));
        mx1 = fmaxf(mx1, __shfl_xor_sync(0xffffffffu, mx1, 1));
        mx1 = fmaxf(mx1, __shfl_xor_sync(0xffffffffu, mx1, 2));
        float mn0 = fmaxf(m0r, mx0), mn1 = fmaxf(m1r, mx1);
        float sc0 = __expf(m0r - mn0), sc1 = __expf(m1r - mn1);
        m0r = mn0; m1r = mn1;

        float sum0 = 0.f, sum1 = 0.f;
        unsigned ph[16];
        #pragma unroll
        for (int nt = 0; nt < 8; nt++) {
            float p0 = __expf(S[nt][0] - mn0);
            float p1 = __expf(S[nt][1] - mn0);
            float p2 = __expf(S[nt][2] - mn1);
            float p3 = __expf(S[nt][3] - mn1);
            sum0 += p0 + p1; sum1 += p2 + p3;
            ph[2 * nt]     = pack2h(p0, p1);
            ph[2 * nt + 1] = pack2h(p2, p3);
        }
        sum0 += __shfl_xor_sync(0xffffffffu, sum0, 1);
        sum0 += __shfl_xor_sync(0xffffffffu, sum0, 2);
        sum1 += __shfl_xor_sync(0xffffffffu, sum1, 1);
        sum1 += __shfl_xor_sync(0xffffffffu, sum1, 2);
        l0r = l0r * sc0 + sum0;
        l1r = l1r * sc1 + sum1;

        #pragma unroll
        for (int dt = 0; dt < 16; dt++) {
            O[dt][0] *= sc0; O[dt][1] *= sc0;
            O[dt][2] *= sc1; O[dt][3] *= sc1;
        }

        // ---- O += P V  (1-term fp16) ----
        #pragma unroll
        for (int ks = 0; ks < 4; ks++) {
            unsigned pa[4] = {ph[4 * ks], ph[4 * ks + 1], ph[4 * ks + 2], ph[4 * ks + 3]};
            #pragma unroll
            for (int dt = 0; dt < 16; dt += 2) {
                unsigned voff = v4Off + (unsigned)((ks * 16 * QSTR + dt * 8) * 2);
                unsigned vh4[4];
                ldsm_x4t(vh4, base + OFF_VH * 4 + voff);
                mma16816h(O[dt],     pa, vh4);
                mma16816h(O[dt + 1], pa, vh4 + 2);
            }
        }
    }

    // ---- epilogue: normalize + fp16 store ----
    float inv0 = 1.f / l0r, inv1 = 1.f / l1r;
    const int rg0 = q0 + wm * 16 + g;
    #pragma unroll
    for (int dt = 0; dt < 16; dt++) {
        int col = dt * 8 + 2 * t4;
        size_t idx0 = (((size_t)b * TSEQ + rg0) * CDIM + h * HD + col) >> 1;
        size_t idx1 = (((size_t)b * TSEQ + rg0 + 8) * CDIM + h * HD + col) >> 1;
        att[idx0] = pack2h(O[dt][0] * inv0, O[dt][1] * inv0);
        att[idx1] = pack2h(O[dt][2] * inv1, O[dt][3] * inv1);
    }
}

// ---------------------------------------------------------------------------
extern "C" void kernel_launch(void* const* d_in, const int* in_sizes, int n_in,
                              void* d_out, int out_size)
{
    const float* x      = (const float*)d_in[0];
    const float* w_attn = (const float*)d_in[1];
    const float* b_attn = (const float*)d_in[2];
    const float* w_proj = (const float*)d_in[3];
    const float* b_proj = (const float*)d_in[4];
    float* out = (float*)d_out;

    unsigned *xh, *wah, *wph, *att;
    float *qkv;
    cudaGetSymbolAddress((void**)&xh,  g_xh);
    cudaGetSymbolAddress((void**)&wah, g_wah);
    cudaGetSymbolAddress((void**)&wph, g_wph);
    cudaGetSymbolAddress((void**)&qkv, g_qkv);
    cudaGetSymbolAddress((void**)&att, g_att);

    cudaFuncSetAttribute(gemm_f16cp_kernel,
                         cudaFuncAttributeMaxDynamicSharedMemorySize, GSMEM);
    cudaFuncSetAttribute(flash_mma_kernel,
                         cudaFuncAttributeMaxDynamicSharedMemorySize, FLASH_SMEM);

    const int M = BDIM * TSEQ;  // 4096

    // 0) one-time fp32 -> fp16 conversion
    int n2x = BDIM * TSEQ * CDIM / 2;
    int n2a = CDIM * 3 * CDIM / 2;
    int n2p = CDIM * CDIM / 2;
    f2h_kernel<<<(n2x + 255) / 256, 256>>>((const float2*)x,      xh,  n2x);
    f2h_kernel<<<(n2a + 255) / 256, 256>>>((const float2*)w_attn, wah, n2a);
    f2h_kernel<<<(n2p + 255) / 256, 256>>>((const float2*)w_proj, wph, n2p);

    // 1) QKV = x @ w_attn + b_attn    (fp16 in, fp32 out)
    gemm_f16cp_kernel<<<dim3(3 * CDIM / GBN, M / GBM), 256, GSMEM>>>(
        (const __half*)xh, (const __half*)wah, b_attn, qkv, M, 3 * CDIM, CDIM);

    // 2) Flash attention (QK bf16 3-term, PV fp16 1-term) -> fp16 att
    flash_mma_kernel<<<dim3(TSEQ / FQ, NHEAD, BDIM), 256, FLASH_SMEM>>>(qkv, att);

    // 3) out = att @ w_proj + b_proj  (fp16 in, fp32 out)
    gemm_f16cp_kernel<<<dim3(CDIM / GBN, M / GBM), 256, GSMEM>>>(
        (const __half*)att, (const __half*)wph, b_proj, out, M, CDIM, CDIM);
}

// round 15
// speedup vs baseline: 1.1557x; 1.1557x over previous
#include <cuda_runtime.h>
#include <cuda_bf16.h>
#include <cuda_fp16.h>
#include <math.h>

#define BDIM  2
#define TSEQ  2048
#define CDIM  2048
#define NHEAD 16
#define HD    128

// ---------------- device-global scratch (no runtime allocation) ----------------
__device__ unsigned g_xh [(size_t)BDIM * TSEQ * CDIM / 2];       // x fp16 pairs
__device__ unsigned g_wah[(size_t)CDIM * 3 * CDIM / 2];          // w_attn fp16 pairs
__device__ unsigned g_wph[(size_t)CDIM * CDIM / 2];              // w_proj fp16 pairs
__device__ unsigned g_qkh[(size_t)BDIM * TSEQ * 2 * CDIM / 2];   // Q,K bf16-hi pairs [B,T,2C]
__device__ unsigned g_qkl[(size_t)BDIM * TSEQ * 2 * CDIM / 2];   // Q,K bf16-lo pairs
__device__ unsigned g_vh [(size_t)BDIM * TSEQ * CDIM / 2];       // V fp16 pairs [B,T,C]
__device__ unsigned g_att[(size_t)BDIM * TSEQ * CDIM / 2];       // att fp16 pairs

// ---------------- helpers ----------------
__device__ __forceinline__ unsigned smem_u32(const void* p) {
    unsigned a;
    asm("{ .reg .u64 t; cvta.to.shared.u64 t, %1; cvt.u32.u64 %0, t; }"
        : "=r"(a) : "l"(p));
    return a;
}

__device__ __forceinline__ unsigned pack2h(float x, float y) {
    unsigned r;
    asm("cvt.rn.f16x2.f32 %0, %1, %2;" : "=r"(r) : "f"(y), "f"(x));
    return r;
}

__device__ __forceinline__ void split2(float x, float y, unsigned& hi, unsigned& lo) {
    unsigned h;
    asm("cvt.rn.bf16x2.f32 %0, %1, %2;" : "=r"(h) : "f"(y), "f"(x));
    float hx = __uint_as_float(h << 16);
    float hy = __uint_as_float(h & 0xffff0000u);
    float rx = x - hx;
    float ry = y - hy;
    unsigned l;
    asm("cvt.rn.bf16x2.f32 %0, %1, %2;" : "=r"(l) : "f"(ry), "f"(rx));
    hi = h; lo = l;
}

// bf16 mma (flash QK)
__device__ __forceinline__ void mma16816(float* d, const unsigned* a, const unsigned* b) {
    asm("mma.sync.aligned.m16n8k16.row.col.f32.bf16.bf16.f32 "
        "{%0,%1,%2,%3}, {%4,%5,%6,%7}, {%8,%9}, {%0,%1,%2,%3};"
        : "+f"(d[0]), "+f"(d[1]), "+f"(d[2]), "+f"(d[3])
        : "r"(a[0]), "r"(a[1]), "r"(a[2]), "r"(a[3]), "r"(b[0]), "r"(b[1]));
}
// fp16 mma (GEMMs + flash PV)
__device__ __forceinline__ void mma16816h(float* d, const unsigned* a, const unsigned* b) {
    asm("mma.sync.aligned.m16n8k16.row.col.f32.f16.f16.f32 "
        "{%0,%1,%2,%3}, {%4,%5,%6,%7}, {%8,%9}, {%0,%1,%2,%3};"
        : "+f"(d[0]), "+f"(d[1]), "+f"(d[2]), "+f"(d[3])
        : "r"(a[0]), "r"(a[1]), "r"(a[2]), "r"(a[3]), "r"(b[0]), "r"(b[1]));
}

__device__ __forceinline__ void ldsm_x4(unsigned* r, unsigned addr) {
    asm volatile("ldmatrix.sync.aligned.m8n8.x4.shared.b16 {%0,%1,%2,%3}, [%4];"
                 : "=r"(r[0]), "=r"(r[1]), "=r"(r[2]), "=r"(r[3]) : "r"(addr));
}
__device__ __forceinline__ void ldsm_x4t(unsigned* r, unsigned addr) {
    asm volatile("ldmatrix.sync.aligned.m8n8.x4.trans.shared.b16 {%0,%1,%2,%3}, [%4];"
                 : "=r"(r[0]), "=r"(r[1]), "=r"(r[2]), "=r"(r[3]) : "r"(addr));
}

__device__ __forceinline__ void cp16(unsigned dst, const void* src) {
    asm volatile("cp.async.cg.shared.global [%0], [%1], 16;" :: "r"(dst), "l"(src) : "memory");
}
__device__ __forceinline__ void cp_commit() {
    asm volatile("cp.async.commit_group;" ::: "memory");
}
template<int N> __device__ __forceinline__ void cp_wait() {
    asm volatile("cp.async.wait_group %0;" :: "n"(N) : "memory");
}

// ---------------------------------------------------------------------------
// fp32 -> fp16 pair conversion (one-time preprocessing)
// ---------------------------------------------------------------------------
__global__ void f2h_kernel(const float2* __restrict__ in, unsigned* __restrict__ out, int n2)
{
    int i = blockIdx.x * blockDim.x + threadIdx.x;
    if (i < n2) {
        float2 v = in[i];
        out[i] = pack2h(v.x, v.y);
    }
}

// ---------------------------------------------------------------------------
// fp16-in GEMM + bias. cp.async 2-stage pipeline. (R11 config: 128x128, BK=32,
// 256 threads, warp tile 64x32, 2 CTAs/SM — proven optimum.)
// OUT=0: fp32 out. OUT=1: QKV split out (Q,K -> bf16 hi/lo; V -> fp16).
// ---------------------------------------------------------------------------
#define GBM 128
#define GBN 128
#define GBK 32
#define ASTRIDE 40      // f16 units per A row (80 B)
#define BSTRIDE 136     // f16 units per B row (272 B)
#define ABYTES (GBM * ASTRIDE * 2)     // 10240
#define BBYTES (GBK * BSTRIDE * 2)     // 8704
#define STAGEB (ABYTES + BBYTES)       // 18944
#define GSMEM  (2 * STAGEB)            // 37888

template<int OUT>
__global__ void __launch_bounds__(256, 2) gemm_f16cp_kernel(
    const __half* __restrict__ A, const __half* __restrict__ B,
    const float* __restrict__ bias, float* __restrict__ Cf,
    unsigned* __restrict__ qkh, unsigned* __restrict__ qkl, unsigned* __restrict__ vh,
    int M, int N, int K)
{
    extern __shared__ char gsm[];
    const unsigned base = smem_u32(gsm);

    const int tid  = threadIdx.x;
    const int lane = tid & 31;
    const int warp = tid >> 5;
    const int wm   = warp >> 2;      // 0..1
    const int wn   = warp & 3;       // 0..3
    const int m0   = blockIdx.y * GBM;
    const int n0   = blockIdx.x * GBN;

    float d[4][4][4];
    #pragma unroll
    for (int i = 0; i < 4; i++)
        #pragma unroll
        for (int j = 0; j < 4; j++)
            #pragma unroll
            for (int c = 0; c < 4; c++) d[i][j][c] = 0.f;

    const unsigned aOff = (unsigned)(((wm * 64 + (lane & 15)) * ASTRIDE + (lane >> 4) * 8) * 2);
    const unsigned bOff = (unsigned)(((lane & 15) * BSTRIDE + wn * 32 + ((lane >> 4) & 1) * 8) * 2);

    auto issue = [&](int it, int s) {
        int k0 = it * GBK;
        unsigned st = base + s * STAGEB;
        {   int r = tid >> 2, c = tid & 3;
            cp16(st + r * 80 + c * 16, A + (size_t)(m0 + r) * K + k0 + c * 8); }
        {   int ch = tid + 256; int r = ch >> 2, c = ch & 3;
            cp16(st + r * 80 + c * 16, A + (size_t)(m0 + r) * K + k0 + c * 8); }
        {   int r = tid >> 4, c = tid & 15;
            cp16(st + ABYTES + r * 272 + c * 16, B + (size_t)(k0 + r) * N + n0 + c * 8); }
        {   int ch = tid + 256; int r = ch >> 4, c = ch & 15;
            cp16(st + ABYTES + r * 272 + c * 16, B + (size_t)(k0 + r) * N + n0 + c * 8); }
        cp_commit();
    };

    const int iters = K / GBK;
    issue(0, 0);

    for (int it = 0; it < iters; it++) {
        const int s = it & 1;
        if (it + 1 < iters) {
            issue(it + 1, s ^ 1);
            cp_wait<1>();
        } else {
            cp_wait<0>();
        }
        __syncthreads();

        const unsigned aB = base + s * STAGEB + aOff;
        const unsigned bB = base + s * STAGEB + ABYTES + bOff;

        #pragma unroll
        for (int kc = 0; kc < GBK; kc += 16) {
            unsigned ah[4][4], bh[2][4];
            #pragma unroll
            for (int tm = 0; tm < 4; tm++)
                ldsm_x4(ah[tm], aB + tm * (16 * ASTRIDE * 2) + kc * 2);
            #pragma unroll
            for (int t2 = 0; t2 < 2; t2++)
                ldsm_x4t(bh[t2], bB + kc * (BSTRIDE * 2) + t2 * 32);
            #pragma unroll
            for (int tm = 0; tm < 4; tm++)
                #pragma unroll
                for (int tn = 0; tn < 4; tn++)
                    mma16816h(d[tm][tn], ah[tm], bh[tn >> 1] + (tn & 1) * 2);
        }
        __syncthreads();
    }

    // epilogue
    const int g = lane >> 2, t4 = lane & 3;
    const bool isV = (n0 >= 2 * CDIM);
    #pragma unroll
    for (int tn = 0; tn < 4; tn++) {
        int col = n0 + wn * 32 + tn * 8 + t4 * 2;
        float bx = bias[col], by = bias[col + 1];
        #pragma unroll
        for (int tm = 0; tm < 4; tm++) {
            int row0 = m0 + wm * 64 + tm * 16 + g;
            float v0 = d[tm][tn][0] + bx, v1 = d[tm][tn][1] + by;
            float v2 = d[tm][tn][2] + bx, v3 = d[tm][tn][3] + by;
            if (OUT == 0) {
                *(float2*)(Cf + (size_t)row0 * N + col)       = make_float2(v0, v1);
                *(float2*)(Cf + (size_t)(row0 + 8) * N + col) = make_float2(v2, v3);
            } else if (!isV) {
                unsigned hh, ll;
                split2(v0, v1, hh, ll);
                size_t idx = ((size_t)row0 * (2 * CDIM) + col) >> 1;
                qkh[idx] = hh; qkl[idx] = ll;
                split2(v2, v3, hh, ll);
                idx = ((size_t)(row0 + 8) * (2 * CDIM) + col) >> 1;
                qkh[idx] = hh; qkl[idx] = ll;
            } else {
                int colv = col - 2 * CDIM;
                vh[((size_t)row0 * CDIM + colv) >> 1]       = pack2h(v0, v1);
                vh[((size_t)(row0 + 8) * CDIM + colv) >> 1] = pack2h(v2, v3);
            }
        }
    }
}

// ---------------------------------------------------------------------------
// Flash attention (causal): QK = 3-term bf16, PV = 1-term fp16.
// Inputs pre-split (Q,K bf16 hi/lo; V fp16) — inner loop is pure
// cp.async (double-buffered KV) -> ldsm -> mma. Scale folded into S.
// 128 queries x 64-key tiles, 8 warps. Heavy (high-qi) blocks first.
// ---------------------------------------------------------------------------
#define FQ 128
#define FK 64
#define QSTR 136          // 16-bit units per row (272 B)

// byte offsets in dynamic smem
#define FOFF_QH 0
#define FOFF_QL 34816
#define FOFF_KV 69632          // stage base
#define FKV_KH 0
#define FKV_KL 17408
#define FKV_VH 34816
#define FKV_STAGE 52224
#define FLASH_SMEM (FOFF_KV + 2 * FKV_STAGE)   // 174080 bytes

__global__ void __launch_bounds__(256, 1) flash_mma_kernel(
    const char* __restrict__ qkh, const char* __restrict__ qkl,
    const char* __restrict__ vh, unsigned* __restrict__ att)
{
    extern __shared__ unsigned fsm[];
    const unsigned base = smem_u32(fsm);

    const int tid  = threadIdx.x;
    const int lane = tid & 31;
    const int wm   = tid >> 5;          // 0..7 : 16 query rows each
    const int g    = lane >> 2;
    const int t4   = lane & 3;

    const int qi = (int)gridDim.x - 1 - (int)blockIdx.x;   // heavy blocks first
    const int h  = blockIdx.y;
    const int b  = blockIdx.z;
    const int q0 = qi * FQ;
    const float sc_att = 0.08838834764831844f;  // 1/sqrt(128)

    // ---- async load Q (hi+lo), then KV tile 0 ----
    #pragma unroll
    for (int i = 0; i < 8; i++) {
        int ch = tid + i * 256;         // 0..2047
        int r = ch >> 4, c = ch & 15;
        unsigned dd = (unsigned)(r * 272 + c * 16);
        size_t so = ((size_t)((size_t)b * TSEQ + q0 + r) * 2 * CDIM + h * HD + c * 8) * 2;
        cp16(base + FOFF_QH + dd, qkh + so);
        cp16(base + FOFF_QL + dd, qkl + so);
    }
    cp_commit();

    #define KV_ISSUE(j, s) {                                                        \
        unsigned sb = base + FOFF_KV + (s) * FKV_STAGE;                             \
        _Pragma("unroll")                                                           \
        for (int i = 0; i < 4; i++) {                                               \
            int ch = tid + i * 256;      /* 0..1023 */                              \
            int r = ch >> 4, c = ch & 15;                                           \
            unsigned dd = (unsigned)(r * 272 + c * 16);                             \
            size_t kq = ((size_t)((size_t)b * TSEQ + (j) * FK + r) * 2 * CDIM       \
                         + CDIM + h * HD + c * 8) * 2;                              \
            size_t vv = ((size_t)((size_t)b * TSEQ + (j) * FK + r) * CDIM           \
                         + h * HD + c * 8) * 2;                                     \
            cp16(sb + FKV_KH + dd, qkh + kq);                                       \
            cp16(sb + FKV_KL + dd, qkl + kq);                                       \
            cp16(sb + FKV_VH + dd, vh + vv);                                        \
        }                                                                           \
        cp_commit(); }

    KV_ISSUE(0, 0);
    cp_wait<1>();          // Q group retired
    __syncthreads();

    // hoist Qh A-fragments (8 k-steps)
    unsigned qh[8][4];
    const unsigned aoff = (unsigned)(((wm * 16 + (lane & 15)) * QSTR + (lane >> 4) * 8) * 2);
    #pragma unroll
    for (int ks = 0; ks < 8; ks++)
        ldsm_x4(qh[ks], base + FOFF_QH + aoff + ks * 32);

    float m0r = -INFINITY, m1r = -INFINITY, l0r = 0.f, l1r = 0.f;
    float O[16][4];
    #pragma unroll
    for (int dt = 0; dt < 16; dt++)
        #pragma unroll
        for (int c = 0; c < 4; c++) O[dt][c] = 0.f;

    const unsigned k4Off = (unsigned)(
        (((lane & 7) + ((lane >> 4) & 1) * 8) * QSTR + ((lane >> 3) & 1) * 8) * 2);
    const unsigned v4Off = (unsigned)(
        ((lane & 15) * QSTR + ((lane >> 4) & 1) * 8) * 2);

    const int jmax = 2 * qi + 2;
    for (int j = 0; j < jmax; j++) {
        const int s = j & 1;
        if (j + 1 < jmax) {
            KV_ISSUE(j + 1, s ^ 1);
            cp_wait<1>();
        } else {
            cp_wait<0>();
        }
        __syncthreads();

        const unsigned kHiB = base + FOFF_KV + s * FKV_STAGE + FKV_KH;
        const unsigned kLoB = base + FOFF_KV + s * FKV_STAGE + FKV_KL;
        const unsigned vHiB = base + FOFF_KV + s * FKV_STAGE + FKV_VH;

        // ---- S = Q K^T (3-term bf16) ----
        float S[8][4];
        #pragma unroll
        for (int nt = 0; nt < 8; nt++)
            #pragma unroll
            for (int c = 0; c < 4; c++) S[nt][c] = 0.f;

        #pragma unroll
        for (int ks = 0; ks < 8; ks++) {
            unsigned ql_[4];
            ldsm_x4(ql_, base + FOFF_QL + aoff + ks * 32);
            #pragma unroll
            for (int nt = 0; nt < 8; nt += 2) {
                unsigned koff = k4Off + (unsigned)((nt * 8 * QSTR + ks * 16) * 2);
                unsigned kh4[4], kl4[4];
                ldsm_x4(kh4, kHiB + koff);
                ldsm_x4(kl4, kLoB + koff);
                mma16816(S[nt],     qh[ks], kh4);
                mma16816(S[nt],     qh[ks], kl4);
                mma16816(S[nt],     ql_,    kh4);
                mma16816(S[nt + 1], qh[ks], kh4 + 2);
                mma16816(S[nt + 1], qh[ks], kl4 + 2);
                mma16816(S[nt + 1], ql_,    kh4 + 2);
            }
        }

        // scale
        #pragma unroll
        for (int nt = 0; nt < 8; nt++)
            #pragma unroll
            for (int c = 0; c < 4; c++) S[nt][c] *= sc_att;

        // ---- causal mask (near-diagonal tiles only) ----
        const int rg0 = q0 + wm * 16 + g;
        const int rg1 = rg0 + 8;
        if (j * FK + FK - 1 > q0 + wm * 16) {
            #pragma unroll
            for (int nt = 0; nt < 8; nt++) {
                int kg = j * FK + nt * 8 + 2 * t4;
                if (kg     > rg0) S[nt][0] = -INFINITY;
                if (kg + 1 > rg0) S[nt][1] = -INFINITY;
                if (kg     > rg1) S[nt][2] = -INFINITY;
                if (kg + 1 > rg1) S[nt][3] = -INFINITY;
            }
        }

        // ---- online softmax ----
        float mx0 = -INFINITY, mx1 = -INFINITY;
        #pragma unroll
        for (int nt = 0; nt < 8; nt++) {
            mx0 = fmaxf(mx0, fmaxf(S[nt][0], S[nt][1]));
            mx1 = fmaxf(mx1, fmaxf(S[nt][2], S[nt][3]));
        }
        mx0 = fmaxf(mx0, __shfl_xor_sync(0xffffffffu, mx0, 1));
        mx0 = fmaxf(mx0, __shfl_xor_sync(0xffffffffu, mx0, 2));
        mx1 = fmaxf(mx1, __shfl_xor_sync(0xffffffffu, mx1, 1));
        mx1 = fmaxf(mx1, __shfl_xor_sync(0xffffffffu, mx1, 2));
        float mn0 = fmaxf(m0r, mx0), mn1 = fmaxf(m1r, mx1);
        float sc0 = __expf(m0r - mn0), sc1 = __expf(m1r - mn1);
        m0r = mn0; m1r = mn1;

        float sum0 = 0.f, sum1 = 0.f;
        unsigned ph[16];
        #pragma unroll
        for (int nt = 0; nt < 8; nt++) {
            float p0 = __expf(S[nt][0] - mn0);
            float p1 = __expf(S[nt][1] - mn0);
            float p2 = __expf(S[nt][2] - mn1);
            float p3 = __expf(S[nt][3] - mn1);
            sum0 += p0 + p1; sum1 += p2 + p3;
            ph[2 * nt]     = pack2h(p0, p1);
            ph[2 * nt + 1] = pack2h(p2, p3);
        }
        sum0 += __shfl_xor_sync(0xffffffffu, sum0, 1);
        sum0 += __shfl_xor_sync(0xffffffffu, sum0, 2);
        sum1 += __shfl_xor_sync(0xffffffffu, sum1, 1);
        sum1 += __shfl_xor_sync(0xffffffffu, sum1, 2);
        l0r = l0r * sc0 + sum0;
        l1r = l1r * sc1 + sum1;

        #pragma unroll
        for (int dt = 0; dt < 16; dt++) {
            O[dt][0] *= sc0; O[dt][1] *= sc0;
            O[dt][2] *= sc1; O[dt][3] *= sc1;
        }

        // ---- O += P V  (1-term fp16) ----
        #pragma unroll
        for (int ks = 0; ks < 4; ks++) {
            unsigned pa[4] = {ph[4 * ks], ph[4 * ks + 1], ph[4 * ks + 2], ph[4 * ks + 3]};
            #pragma unroll
            for (int dt = 0; dt < 16; dt += 2) {
                unsigned voff = v4Off + (unsigned)((ks * 16 * QSTR + dt * 8) * 2);
                unsigned vh4[4];
                ldsm_x4t(vh4, vHiB + voff);
                mma16816h(O[dt],     pa, vh4);
                mma16816h(O[dt + 1], pa, vh4 + 2);
            }
        }
        __syncthreads();   // stage s fully consumed before next iter overwrites
    }

    // ---- epilogue: normalize + fp16 store ----
    float inv0 = 1.f / l0r, inv1 = 1.f / l1r;
    const int rg0 = q0 + wm * 16 + g;
    #pragma unroll
    for (int dt = 0; dt < 16; dt++) {
        int col = dt * 8 + 2 * t4;
        size_t idx0 = (((size_t)b * TSEQ + rg0) * CDIM + h * HD + col) >> 1;
        size_t idx1 = (((size_t)b * TSEQ + rg0 + 8) * CDIM + h * HD + col) >> 1;
        att[idx0] = pack2h(O[dt][0] * inv0, O[dt][1] * inv0);
        att[idx1] = pack2h(O[dt][2] * inv1, O[dt][3] * inv1);
    }
}

// ---------------------------------------------------------------------------
extern "C" void kernel_launch(void* const* d_in, const int* in_sizes, int n_in,
                              void* d_out, int out_size)
{
    const float* x      = (const float*)d_in[0];
    const float* w_attn = (const float*)d_in[1];
    const float* b_attn = (const float*)d_in[2];
    const float* w_proj = (const float*)d_in[3];
    const float* b_proj = (const float*)d_in[4];
    float* out = (float*)d_out;

    unsigned *xh, *wah, *wph, *qkh, *qkl, *vh, *att;
    cudaGetSymbolAddress((void**)&xh,  g_xh);
    cudaGetSymbolAddress((void**)&wah, g_wah);
    cudaGetSymbolAddress((void**)&wph, g_wph);
    cudaGetSymbolAddress((void**)&qkh, g_qkh);
    cudaGetSymbolAddress((void**)&qkl, g_qkl);
    cudaGetSymbolAddress((void**)&vh,  g_vh);
    cudaGetSymbolAddress((void**)&att, g_att);

    cudaFuncSetAttribute(gemm_f16cp_kernel<0>,
                         cudaFuncAttributeMaxDynamicSharedMemorySize, GSMEM);
    cudaFuncSetAttribute(gemm_f16cp_kernel<1>,
                         cudaFuncAttributeMaxDynamicSharedMemorySize, GSMEM);
    cudaFuncSetAttribute(flash_mma_kernel,
                         cudaFuncAttributeMaxDynamicSharedMemorySize, FLASH_SMEM);

    const int M = BDIM * TSEQ;  // 4096

    // 0) one-time fp32 -> fp16 conversion of GEMM inputs
    int n2x = BDIM * TSEQ * CDIM / 2;
    int n2a = CDIM * 3 * CDIM / 2;
    int n2p = CDIM * CDIM / 2;
    f2h_kernel<<<(n2x + 255) / 256, 256>>>((const float2*)x,      xh,  n2x);
    f2h_kernel<<<(n2a + 255) / 256, 256>>>((const float2*)w_attn, wah, n2a);
    f2h_kernel<<<(n2p + 255) / 256, 256>>>((const float2*)w_proj, wph, n2p);

    // 1) QKV GEMM -> Q,K split bf16 hi/lo; V fp16
    gemm_f16cp_kernel<1><<<dim3(3 * CDIM / GBN, M / GBM), 256, GSMEM>>>(
        (const __half*)xh, (const __half*)wah, b_attn, nullptr,
        qkh, qkl, vh, M, 3 * CDIM, CDIM);

    // 2) Flash attention -> fp16 att
    flash_mma_kernel<<<dim3(TSEQ / FQ, NHEAD, BDIM), 256, FLASH_SMEM>>>(
        (const char*)qkh, (const char*)qkl, (const char*)vh, att);

    // 3) out = att @ w_proj + b_proj  (fp32 out)
    gemm_f16cp_kernel<0><<<dim3(CDIM / GBN, M / GBM), 256, GSMEM>>>(
        (const __half*)att, (const __half*)wph, b_proj, out,
        nullptr, nullptr, nullptr, M, CDIM, CDIM);
}

// round 16
// speedup vs baseline: 1.3331x; 1.1534x over previous
#include <cuda_runtime.h>
#include <cuda_bf16.h>
#include <cuda_fp16.h>
#include <math.h>

#define BDIM  2
#define TSEQ  2048
#define CDIM  2048
#define NHEAD 16
#define HD    128

// ---------------- device-global scratch (no runtime allocation) ----------------
__device__ unsigned g_xh  [(size_t)BDIM * TSEQ * CDIM / 2];      // x fp16 pairs
__device__ unsigned g_wah [(size_t)CDIM * 3 * CDIM / 2];         // w_attn fp16 pairs
__device__ unsigned g_wph [(size_t)CDIM * CDIM / 2];             // w_proj fp16 pairs
__device__ unsigned g_qkvh[(size_t)BDIM * TSEQ * 3 * CDIM / 2];  // qkv fp16 pairs [B,T,3C]
__device__ unsigned g_att [(size_t)BDIM * TSEQ * CDIM / 2];      // att fp16 pairs

// ---------------- helpers ----------------
__device__ __forceinline__ unsigned smem_u32(const void* p) {
    unsigned a;
    asm("{ .reg .u64 t; cvta.to.shared.u64 t, %1; cvt.u32.u64 %0, t; }"
        : "=r"(a) : "l"(p));
    return a;
}

__device__ __forceinline__ unsigned pack2h(float x, float y) {
    unsigned r;
    asm("cvt.rn.f16x2.f32 %0, %1, %2;" : "=r"(r) : "f"(y), "f"(x));
    return r;
}

// fp16 mma (all matmuls)
__device__ __forceinline__ void mma16816h(float* d, const unsigned* a, const unsigned* b) {
    asm("mma.sync.aligned.m16n8k16.row.col.f32.f16.f16.f32 "
        "{%0,%1,%2,%3}, {%4,%5,%6,%7}, {%8,%9}, {%0,%1,%2,%3};"
        : "+f"(d[0]), "+f"(d[1]), "+f"(d[2]), "+f"(d[3])
        : "r"(a[0]), "r"(a[1]), "r"(a[2]), "r"(a[3]), "r"(b[0]), "r"(b[1]));
}

__device__ __forceinline__ void ldsm_x4(unsigned* r, unsigned addr) {
    asm volatile("ldmatrix.sync.aligned.m8n8.x4.shared.b16 {%0,%1,%2,%3}, [%4];"
                 : "=r"(r[0]), "=r"(r[1]), "=r"(r[2]), "=r"(r[3]) : "r"(addr));
}
__device__ __forceinline__ void ldsm_x4t(unsigned* r, unsigned addr) {
    asm volatile("ldmatrix.sync.aligned.m8n8.x4.trans.shared.b16 {%0,%1,%2,%3}, [%4];"
                 : "=r"(r[0]), "=r"(r[1]), "=r"(r[2]), "=r"(r[3]) : "r"(addr));
}

__device__ __forceinline__ void cp16(unsigned dst, const void* src) {
    asm volatile("cp.async.cg.shared.global [%0], [%1], 16;" :: "r"(dst), "l"(src) : "memory");
}
__device__ __forceinline__ void cp_commit() {
    asm volatile("cp.async.commit_group;" ::: "memory");
}
template<int N> __device__ __forceinline__ void cp_wait() {
    asm volatile("cp.async.wait_group %0;" :: "n"(N) : "memory");
}

// ---------------------------------------------------------------------------
// fp32 -> fp16 pair conversion (one-time preprocessing)
// ---------------------------------------------------------------------------
__global__ void f2h_kernel(const float2* __restrict__ in, unsigned* __restrict__ out, int n2)
{
    int i = blockIdx.x * blockDim.x + threadIdx.x;
    if (i < n2) {
        float2 v = in[i];
        out[i] = pack2h(v.x, v.y);
    }
}

// ---------------------------------------------------------------------------
// fp16-in GEMM + bias. cp.async 2-stage pipeline. (R11 config: 128x128, BK=32,
// 256 threads, warp tile 64x32, 2 CTAs/SM — proven optimum.)
// OUT=0: fp32 out. OUT=1: fp16-pair out (QKV).
// ---------------------------------------------------------------------------
#define GBM 128
#define GBN 128
#define GBK 32
#define ASTRIDE 40      // f16 units per A row (80 B)
#define BSTRIDE 136     // f16 units per B row (272 B)
#define ABYTES (GBM * ASTRIDE * 2)     // 10240
#define BBYTES (GBK * BSTRIDE * 2)     // 8704
#define STAGEB (ABYTES + BBYTES)       // 18944
#define GSMEM  (2 * STAGEB)            // 37888

template<int OUT>
__global__ void __launch_bounds__(256, 2) gemm_f16cp_kernel(
    const __half* __restrict__ A, const __half* __restrict__ B,
    const float* __restrict__ bias, float* __restrict__ Cf,
    unsigned* __restrict__ Ch, int M, int N, int K)
{
    extern __shared__ char gsm[];
    const unsigned base = smem_u32(gsm);

    const int tid  = threadIdx.x;
    const int lane = tid & 31;
    const int warp = tid >> 5;
    const int wm   = warp >> 2;      // 0..1
    const int wn   = warp & 3;       // 0..3
    const int m0   = blockIdx.y * GBM;
    const int n0   = blockIdx.x * GBN;

    float d[4][4][4];
    #pragma unroll
    for (int i = 0; i < 4; i++)
        #pragma unroll
        for (int j = 0; j < 4; j++)
            #pragma unroll
            for (int c = 0; c < 4; c++) d[i][j][c] = 0.f;

    const unsigned aOff = (unsigned)(((wm * 64 + (lane & 15)) * ASTRIDE + (lane >> 4) * 8) * 2);
    const unsigned bOff = (unsigned)(((lane & 15) * BSTRIDE + wn * 32 + ((lane >> 4) & 1) * 8) * 2);

    auto issue = [&](int it, int s) {
        int k0 = it * GBK;
        unsigned st = base + s * STAGEB;
        {   int r = tid >> 2, c = tid & 3;
            cp16(st + r * 80 + c * 16, A + (size_t)(m0 + r) * K + k0 + c * 8); }
        {   int ch = tid + 256; int r = ch >> 2, c = ch & 3;
            cp16(st + r * 80 + c * 16, A + (size_t)(m0 + r) * K + k0 + c * 8); }
        {   int r = tid >> 4, c = tid & 15;
            cp16(st + ABYTES + r * 272 + c * 16, B + (size_t)(k0 + r) * N + n0 + c * 8); }
        {   int ch = tid + 256; int r = ch >> 4, c = ch & 15;
            cp16(st + ABYTES + r * 272 + c * 16, B + (size_t)(k0 + r) * N + n0 + c * 8); }
        cp_commit();
    };

    const int iters = K / GBK;
    issue(0, 0);

    for (int it = 0; it < iters; it++) {
        const int s = it & 1;
        if (it + 1 < iters) {
            issue(it + 1, s ^ 1);
            cp_wait<1>();
        } else {
            cp_wait<0>();
        }
        __syncthreads();

        const unsigned aB = base + s * STAGEB + aOff;
        const unsigned bB = base + s * STAGEB + ABYTES + bOff;

        #pragma unroll
        for (int kc = 0; kc < GBK; kc += 16) {
            unsigned ah[4][4], bh[2][4];
            #pragma unroll
            for (int tm = 0; tm < 4; tm++)
                ldsm_x4(ah[tm], aB + tm * (16 * ASTRIDE * 2) + kc * 2);
            #pragma unroll
            for (int t2 = 0; t2 < 2; t2++)
                ldsm_x4t(bh[t2], bB + kc * (BSTRIDE * 2) + t2 * 32);
            #pragma unroll
            for (int tm = 0; tm < 4; tm++)
                #pragma unroll
                for (int tn = 0; tn < 4; tn++)
                    mma16816h(d[tm][tn], ah[tm], bh[tn >> 1] + (tn & 1) * 2);
        }
        __syncthreads();
    }

    // epilogue
    const int g = lane >> 2, t4 = lane & 3;
    #pragma unroll
    for (int tn = 0; tn < 4; tn++) {
        int col = n0 + wn * 32 + tn * 8 + t4 * 2;
        float bx = bias[col], by = bias[col + 1];
        #pragma unroll
        for (int tm = 0; tm < 4; tm++) {
            int row0 = m0 + wm * 64 + tm * 16 + g;
            float v0 = d[tm][tn][0] + bx, v1 = d[tm][tn][1] + by;
            float v2 = d[tm][tn][2] + bx, v3 = d[tm][tn][3] + by;
            if (OUT == 0) {
                *(float2*)(Cf + (size_t)row0 * N + col)       = make_float2(v0, v1);
                *(float2*)(Cf + (size_t)(row0 + 8) * N + col) = make_float2(v2, v3);
            } else {
                Ch[((size_t)row0 * N + col) >> 1]       = pack2h(v0, v1);
                Ch[((size_t)(row0 + 8) * N + col) >> 1] = pack2h(v2, v3);
            }
        }
    }
}

// ---------------------------------------------------------------------------
// Flash attention (causal): QK = 1-term fp16, PV = 1-term fp16.
// qkv fully fp16 (from GEMM1 epilogue). Inner loop: cp.async (double-buffered
// K/V) -> ldsm -> mma; Q fragments fully register-hoisted; scale folded into S.
// 128 queries x 64-key tiles, 8 warps. Heavy (high-qi) blocks first.
// ---------------------------------------------------------------------------
#define FQ 128
#define FK 64
#define QSTR 136          // 16-bit units per row (272 B)

// byte offsets in dynamic smem
#define FOFF_Q  0                  // 34816 B (Q fp16 tile)
#define FOFF_KV 34816              // stage base
#define FKV_K 0
#define FKV_V 17408
#define FKV_STAGE 34816
#define FLASH_SMEM (FOFF_KV + 2 * FKV_STAGE)   // 104448 bytes

__global__ void __launch_bounds__(256, 1) flash_mma_kernel(
    const char* __restrict__ qkv, unsigned* __restrict__ att)
{
    extern __shared__ unsigned fsm[];
    const unsigned base = smem_u32(fsm);

    const int tid  = threadIdx.x;
    const int lane = tid & 31;
    const int wm   = tid >> 5;          // 0..7 : 16 query rows each
    const int g    = lane >> 2;
    const int t4   = lane & 3;

    const int qi = (int)gridDim.x - 1 - (int)blockIdx.x;   // heavy blocks first
    const int h  = blockIdx.y;
    const int b  = blockIdx.z;
    const int q0 = qi * FQ;
    const float sc_att = 0.08838834764831844f;  // 1/sqrt(128)

    // ---- async load Q (fp16), then KV tile 0 ----
    #pragma unroll
    for (int i = 0; i < 8; i++) {
        int ch = tid + i * 256;         // 0..2047
        int r = ch >> 4, c = ch & 15;
        size_t so = ((size_t)((size_t)b * TSEQ + q0 + r) * 3 * CDIM + h * HD) * 2 + c * 16;
        cp16(base + FOFF_Q + (unsigned)(r * 272 + c * 16), qkv + so);
    }
    cp_commit();

    #define KV_ISSUE(j, s) {                                                        \
        unsigned sb = base + FOFF_KV + (s) * FKV_STAGE;                             \
        _Pragma("unroll")                                                           \
        for (int i = 0; i < 4; i++) {                                               \
            int ch = tid + i * 256;      /* 0..1023 */                              \
            int r = ch >> 4, c = ch & 15;                                           \
            unsigned dd = (unsigned)(r * 272 + c * 16);                             \
            size_t ro = ((size_t)((size_t)b * TSEQ + (j) * FK + r) * 3 * CDIM       \
                         + h * HD) * 2 + c * 16;                                    \
            cp16(sb + FKV_K + dd, qkv + ro + CDIM * 2);                             \
            cp16(sb + FKV_V + dd, qkv + ro + 2 * CDIM * 2);                         \
        }                                                                           \
        cp_commit(); }

    KV_ISSUE(0, 0);
    cp_wait<1>();          // Q group retired
    __syncthreads();

    // hoist ALL Q A-fragments (8 k-steps) — Q smem not touched again
    unsigned qh[8][4];
    const unsigned aoff = (unsigned)(((wm * 16 + (lane & 15)) * QSTR + (lane >> 4) * 8) * 2);
    #pragma unroll
    for (int ks = 0; ks < 8; ks++)
        ldsm_x4(qh[ks], base + FOFF_Q + aoff + ks * 32);

    float m0r = -INFINITY, m1r = -INFINITY, l0r = 0.f, l1r = 0.f;
    float O[16][4];
    #pragma unroll
    for (int dt = 0; dt < 16; dt++)
        #pragma unroll
        for (int c = 0; c < 4; c++) O[dt][c] = 0.f;

    const unsigned k4Off = (unsigned)(
        (((lane & 7) + ((lane >> 4) & 1) * 8) * QSTR + ((lane >> 3) & 1) * 8) * 2);
    const unsigned v4Off = (unsigned)(
        ((lane & 15) * QSTR + ((lane >> 4) & 1) * 8) * 2);

    const int jmax = 2 * qi + 2;
    for (int j = 0; j < jmax; j++) {
        const int s = j & 1;
        if (j + 1 < jmax) {
            KV_ISSUE(j + 1, s ^ 1);
            cp_wait<1>();
        } else {
            cp_wait<0>();
        }
        __syncthreads();

        const unsigned kB = base + FOFF_KV + s * FKV_STAGE + FKV_K;
        const unsigned vB = base + FOFF_KV + s * FKV_STAGE + FKV_V;

        // ---- S = Q K^T (1-term fp16) ----
        float S[8][4];
        #pragma unroll
        for (int nt = 0; nt < 8; nt++)
            #pragma unroll
            for (int c = 0; c < 4; c++) S[nt][c] = 0.f;

        #pragma unroll
        for (int ks = 0; ks < 8; ks++) {
            #pragma unroll
            for (int nt = 0; nt < 8; nt += 2) {
                unsigned k4[4];
                ldsm_x4(k4, kB + k4Off + (unsigned)((nt * 8 * QSTR + ks * 16) * 2));
                mma16816h(S[nt],     qh[ks], k4);
                mma16816h(S[nt + 1], qh[ks], k4 + 2);
            }
        }

        // scale
        #pragma unroll
        for (int nt = 0; nt < 8; nt++)
            #pragma unroll
            for (int c = 0; c < 4; c++) S[nt][c] *= sc_att;

        // ---- causal mask (near-diagonal tiles only) ----
        const int rg0 = q0 + wm * 16 + g;
        const int rg1 = rg0 + 8;
        if (j * FK + FK - 1 > q0 + wm * 16) {
            #pragma unroll
            for (int nt = 0; nt < 8; nt++) {
                int kg = j * FK + nt * 8 + 2 * t4;
                if (kg     > rg0) S[nt][0] = -INFINITY;
                if (kg + 1 > rg0) S[nt][1] = -INFINITY;
                if (kg     > rg1) S[nt][2] = -INFINITY;
                if (kg + 1 > rg1) S[nt][3] = -INFINITY;
            }
        }

        // ---- online softmax ----
        float mx0 = -INFINITY, mx1 = -INFINITY;
        #pragma unroll
        for (int nt = 0; nt < 8; nt++) {
            mx0 = fmaxf(mx0, fmaxf(S[nt][0], S[nt][1]));
            mx1 = fmaxf(mx1, fmaxf(S[nt][2], S[nt][3]));
        }
        mx0 = fmaxf(mx0, __shfl_xor_sync(0xffffffffu, mx0, 1));
        mx0 = fmaxf(mx0, __shfl_xor_sync(0xffffffffu, mx0, 2));
        mx1 = fmaxf(mx1, __shfl_xor_sync(0xffffffffu, mx1, 1));
        mx1 = fmaxf(mx1, __shfl_xor_sync(0xffffffffu, mx1, 2));
        float mn0 = fmaxf(m0r, mx0), mn1 = fmaxf(m1r, mx1);
        float sc0 = __expf(m0r - mn0), sc1 = __expf(m1r - mn1);
        m0r = mn0; m1r = mn1;

        float sum0 = 0.f, sum1 = 0.f;
        unsigned ph[16];
        #pragma unroll
        for (int nt = 0; nt < 8; nt++) {
            float p0 = __expf(S[nt][0] - mn0);
            float p1 = __expf(S[nt][1] - mn0);
            float p2 = __expf(S[nt][2] - mn1);
            float p3 = __expf(S[nt][3] - mn1);
            sum0 += p0 + p1; sum1 += p2 + p3;
            ph[2 * nt]     = pack2h(p0, p1);
            ph[2 * nt + 1] = pack2h(p2, p3);
        }
        sum0 += __shfl_xor_sync(0xffffffffu, sum0, 1);
        sum0 += __shfl_xor_sync(0xffffffffu, sum0, 2);
        sum1 += __shfl_xor_sync(0xffffffffu, sum1, 1);
        sum1 += __shfl_xor_sync(0xffffffffu, sum1, 2);
        l0r = l0r * sc0 + sum0;
        l1r = l1r * sc1 + sum1;

        #pragma unroll
        for (int dt = 0; dt < 16; dt++) {
            O[dt][0] *= sc0; O[dt][1] *= sc0;
            O[dt][2] *= sc1; O[dt][3] *= sc1;
        }

        // ---- O += P V  (1-term fp16) ----
        #pragma unroll
        for (int ks = 0; ks < 4; ks++) {
            unsigned pa[4] = {ph[4 * ks], ph[4 * ks + 1], ph[4 * ks + 2], ph[4 * ks + 3]};
            #pragma unroll
            for (int dt = 0; dt < 16; dt += 2) {
                unsigned vh4[4];
                ldsm_x4t(vh4, vB + v4Off + (unsigned)((ks * 16 * QSTR + dt * 8) * 2));
                mma16816h(O[dt],     pa, vh4);
                mma16816h(O[dt + 1], pa, vh4 + 2);
            }
        }
        __syncthreads();   // stage s fully consumed before next iter overwrites
    }

    // ---- epilogue: normalize + fp16 store ----
    float inv0 = 1.f / l0r, inv1 = 1.f / l1r;
    const int rg0 = q0 + wm * 16 + g;
    #pragma unroll
    for (int dt = 0; dt < 16; dt++) {
        int col = dt * 8 + 2 * t4;
        size_t idx0 = (((size_t)b * TSEQ + rg0) * CDIM + h * HD + col) >> 1;
        size_t idx1 = (((size_t)b * TSEQ + rg0 + 8) * CDIM + h * HD + col) >> 1;
        att[idx0] = pack2h(O[dt][0] * inv0, O[dt][1] * inv0);
        att[idx1] = pack2h(O[dt][2] * inv1, O[dt][3] * inv1);
    }
}

// ---------------------------------------------------------------------------
extern "C" void kernel_launch(void* const* d_in, const int* in_sizes, int n_in,
                              void* d_out, int out_size)
{
    const float* x      = (const float*)d_in[0];
    const float* w_attn = (const float*)d_in[1];
    const float* b_attn = (const float*)d_in[2];
    const float* w_proj = (const float*)d_in[3];
    const float* b_proj = (const float*)d_in[4];
    float* out = (float*)d_out;

    unsigned *xh, *wah, *wph, *qkvh, *att;
    cudaGetSymbolAddress((void**)&xh,   g_xh);
    cudaGetSymbolAddress((void**)&wah,  g_wah);
    cudaGetSymbolAddress((void**)&wph,  g_wph);
    cudaGetSymbolAddress((void**)&qkvh, g_qkvh);
    cudaGetSymbolAddress((void**)&att,  g_att);

    cudaFuncSetAttribute(gemm_f16cp_kernel<0>,
                         cudaFuncAttributeMaxDynamicSharedMemorySize, GSMEM);
    cudaFuncSetAttribute(gemm_f16cp_kernel<1>,
                         cudaFuncAttributeMaxDynamicSharedMemorySize, GSMEM);
    cudaFuncSetAttribute(flash_mma_kernel,
                         cudaFuncAttributeMaxDynamicSharedMemorySize, FLASH_SMEM);

    const int M = BDIM * TSEQ;  // 4096

    // 0) one-time fp32 -> fp16 conversion of GEMM inputs
    int n2x = BDIM * TSEQ * CDIM / 2;
    int n2a = CDIM * 3 * CDIM / 2;
    int n2p = CDIM * CDIM / 2;
    f2h_kernel<<<(n2x + 255) / 256, 256>>>((const float2*)x,      xh,  n2x);
    f2h_kernel<<<(n2a + 255) / 256, 256>>>((const float2*)w_attn, wah, n2a);
    f2h_kernel<<<(n2p + 255) / 256, 256>>>((const float2*)w_proj, wph, n2p);

    // 1) QKV = x @ w_attn + b_attn -> fp16 qkv
    gemm_f16cp_kernel<1><<<dim3(3 * CDIM / GBN, M / GBM), 256, GSMEM>>>(
        (const __half*)xh, (const __half*)wah, b_attn, nullptr, qkvh,
        M, 3 * CDIM, CDIM);

    // 2) Flash attention (all fp16) -> fp16 att
    flash_mma_kernel<<<dim3(TSEQ / FQ, NHEAD, BDIM), 256, FLASH_SMEM>>>(
        (const char*)qkvh, att);

    // 3) out = att @ w_proj + b_proj  (fp32 out)
    gemm_f16cp_kernel<0><<<dim3(CDIM / GBN, M / GBM), 256, GSMEM>>>(
        (const __half*)att, (const __half*)wph, b_proj, out, nullptr,
        M, CDIM, CDIM);
}